// round 1
// baseline (speedup 1.0000x reference)
#include <cuda_runtime.h>
#include <math.h>

#define NB 2
#define NV 180
#define NR 32
#define NC 512
#define NPIX 512
#define PI_D 3.14159265358979323846

// Scratch: filtered sinogram, same layout as input (B,V,R,C)
__device__ float g_filt[NB * NV * NR * NC];
// Twiddle table: tw[j] = exp(-2*pi*i*j/512), j in [0,256)
__device__ float g_twr[256];
__device__ float g_twi[256];
// Per-view cos/sin
__device__ float g_cosv[NV];
__device__ float g_sinv[NV];

__global__ void init_tables_kernel() {
    int i = threadIdx.x;
    if (i < 256) {
        double a = -2.0 * PI_D * (double)i / 512.0;
        g_twr[i] = (float)cos(a);
        g_twi[i] = (float)sin(a);
    }
    if (i < NV) {
        double th = (double)i * PI_D / (double)NV;
        g_cosv[i] = (float)cos(th);
        g_sinv[i] = (float)sin(th);
    }
}

// One block filters TWO real rows packed as one complex 512-pt FFT.
// DIF forward (natural in -> bitrev out), ramp multiply in bitrev slots,
// DIT inverse with conj twiddles (bitrev in -> natural out). 1/N folded
// into the ramp scale.
__global__ void __launch_bounds__(256) filter_kernel(const float* __restrict__ sino) {
    __shared__ float sre[512];
    __shared__ float sim[512];
    __shared__ float twr[256];
    __shared__ float twi[256];

    int tid = threadIdx.x;           // 0..255
    int base = blockIdx.x * 2 * NC;  // pair of consecutive rows

    twr[tid] = g_twr[tid];
    twi[tid] = g_twi[tid];
    sre[tid]       = sino[base + tid];
    sre[tid + 256] = sino[base + tid + 256];
    sim[tid]       = sino[base + NC + tid];
    sim[tid + 256] = sino[base + NC + tid + 256];
    __syncthreads();

    // ---- DIF forward ----
    {
        int step = 1;
        for (int len = 512; len >= 2; len >>= 1, step <<= 1) {
            int half = len >> 1;
            int grp = tid / half;
            int j = tid - grp * half;
            int i0 = grp * len + j;
            int i1 = i0 + half;
            int tj = j * step;
            float wr = twr[tj], wi = twi[tj];
            float ar = sre[i0], ai = sim[i0];
            float br = sre[i1], bi = sim[i1];
            sre[i0] = ar + br;
            sim[i0] = ai + bi;
            float dr = ar - br, di = ai - bi;
            sre[i1] = dr * wr - di * wi;
            sim[i1] = dr * wi + di * wr;
            __syncthreads();
        }
    }

    // ---- ramp multiply (slots hold X[bitrev(p)]) ----
    #pragma unroll
    for (int q = 0; q < 2; ++q) {
        int n = tid + q * 256;
        int f = (int)(__brev((unsigned)n) >> 23);
        int m = min(f, 512 - f);
        // ramp = 2*m/512 ; ifft scale = 1/512
        float scale = (float)m * (2.0f / (512.0f * 512.0f));
        sre[n] *= scale;
        sim[n] *= scale;
    }
    __syncthreads();

    // ---- DIT inverse (conj twiddles) ----
    {
        int step = 256;
        for (int len = 2; len <= 512; len <<= 1, step >>= 1) {
            int half = len >> 1;
            int grp = tid / half;
            int j = tid - grp * half;
            int i0 = grp * len + j;
            int i1 = i0 + half;
            int tj = j * step;
            float wr = twr[tj], wi = -twi[tj];
            float ar = sre[i0], ai = sim[i0];
            float br = sre[i1], bi = sim[i1];
            float vr = br * wr - bi * wi;
            float vi = br * wi + bi * wr;
            sre[i0] = ar + vr;
            sim[i0] = ai + vi;
            sre[i1] = ar - vr;
            sim[i1] = ai - vi;
            __syncthreads();
        }
    }

    g_filt[base + tid]            = sre[tid];
    g_filt[base + tid + 256]      = sre[tid + 256];
    g_filt[base + NC + tid]       = sim[tid];
    g_filt[base + NC + tid + 256] = sim[tid + 256];
}

#define TILE 32
#define WIN  52
#define NIMG 4

// Block: 16x16 threads, 32x32 pixel tile (2x2 pixels/thread), 4 (b,r) images.
// Per view, stage only the t-window of each projection row into smem.
__global__ void __launch_bounds__(256) backproj_kernel(float* __restrict__ out) {
    __shared__ float srow[NIMG][WIN];
    __shared__ float scos[NV];
    __shared__ float ssin[NV];

    int tx = threadIdx.x;
    int ty = threadIdx.y;
    int tid = ty * 16 + tx;
    if (tid < NV) {
        scos[tid] = g_cosv[tid];
        ssin[tid] = g_sinv[tid];
    }

    int g  = blockIdx.z;            // 0..15
    int b  = g >> 3;
    int r0 = (g & 7) * NIMG;
    int x0 = blockIdx.x * TILE;
    int y0 = blockIdx.y * TILE;

    float xb = (float)(x0 + tx) - 255.5f;
    float yb = (float)(y0 + ty) - 255.5f;
    float xt = (float)x0 - 255.5f;
    float yt = (float)y0 - 255.5f;

    float acc[2][2][NIMG];
    #pragma unroll
    for (int py = 0; py < 2; ++py)
        #pragma unroll
        for (int px = 0; px < 2; ++px)
            #pragma unroll
            for (int k = 0; k < NIMG; ++k)
                acc[py][px][k] = 0.0f;

    __syncthreads();

    int rowbase = ((b * NV) * NR + r0) * NC;  // advances by NR*NC per view

    for (int v = 0; v < NV; ++v) {
        float c = scos[v], s = ssin[v];

        // window start for this tile/view (uniform across block)
        float tmin = xt * c + yt * s + 255.5f + fminf(31.0f * c, 0.0f) + fminf(31.0f * s, 0.0f);
        int w0 = (int)floorf(tmin) - 1;
        w0 = max(0, min(w0, 465));

        if (tid < NIMG * WIN) {
            int img = tid / WIN;
            int off = tid - img * WIN;
            int gi = min(w0 + off, 511);
            srow[img][off] = g_filt[rowbase + img * NC + gi];
        }
        __syncthreads();

        float t00 = fmaf(xb, c, fmaf(yb, s, 255.5f));
        float c16 = 16.0f * c;
        float s16 = 16.0f * s;

        #pragma unroll
        for (int py = 0; py < 2; ++py) {
            #pragma unroll
            for (int px = 0; px < 2; ++px) {
                float t = t00 + (float)px * c16 + (float)py * s16;
                t = fminf(fmaxf(t, 0.0f), 511.0f);
                float fi = floorf(t);
                int loc = (int)fi - w0;
                float w = t - fi;
                float w1 = 1.0f - w;
                #pragma unroll
                for (int k = 0; k < NIMG; ++k) {
                    float g0v = srow[k][loc];
                    float g1v = srow[k][loc + 1];
                    acc[py][px][k] += g0v * w1 + g1v * w;
                }
            }
        }
        __syncthreads();

        rowbase += NR * NC;
    }

    const float outscale = (float)(PI_D / (double)NV);
    #pragma unroll
    for (int k = 0; k < NIMG; ++k) {
        #pragma unroll
        for (int py = 0; py < 2; ++py) {
            #pragma unroll
            for (int px = 0; px < 2; ++px) {
                int y = y0 + ty + py * 16;
                int x = x0 + tx + px * 16;
                float val = fmaxf(acc[py][px][k] * outscale, 0.0f);
                out[(((b * NR + r0 + k) * NPIX) + y) * NPIX + x] = val;
            }
        }
    }
}

extern "C" void kernel_launch(void* const* d_in, const int* in_sizes, int n_in,
                              void* d_out, int out_size) {
    const float* sino = (const float*)d_in[0];
    float* out = (float*)d_out;
    (void)in_sizes; (void)n_in; (void)out_size;

    init_tables_kernel<<<1, 256>>>();
    filter_kernel<<<NB * NV * NR / 2, 256>>>(sino);
    dim3 bpGrid(NPIX / TILE, NPIX / TILE, (NB * NR) / NIMG);
    dim3 bpBlock(16, 16);
    backproj_kernel<<<bpGrid, bpBlock>>>(out);
}

// round 2
// speedup vs baseline: 1.6131x; 1.6131x over previous
#include <cuda_runtime.h>
#include <cuda_fp16.h>
#include <math.h>

#define NB 2
#define NV 180
#define NR 32
#define NC 512
#define NPIX 512
#define PI_D 3.14159265358979323846

// Filtered sinogram, image-pair packed: g_pack[((b*NV+v)*(NR/2)+rp)*NC + i]
//   = half2( filt[b,v,2rp,i], filt[b,v,2rp+1,i] )
__device__ __half2 g_pack[NB * NV * (NR / 2) * NC + 4];
// Twiddles: tw[j] = exp(-2*pi*i*j/512)
__device__ float g_twr[256];
__device__ float g_twi[256];
__device__ float g_cosv[NV];
__device__ float g_sinv[NV];

__global__ void init_tables_kernel() {
    int i = threadIdx.x;
    if (i < 256) {
        double a = -2.0 * PI_D * (double)i / 512.0;
        g_twr[i] = (float)cos(a);
        g_twi[i] = (float)sin(a);
    }
    if (i < NV) {
        double th = (double)i * PI_D / (double)NV;
        g_cosv[i] = (float)cos(th);
        g_sinv[i] = (float)sin(th);
    }
}

// One block filters TWO consecutive real rows packed as one complex 512-pt FFT.
// DIF forward -> ramp multiply in bit-reversed slots -> DIT inverse (conj).
// Result written as image-pair-packed half2.
__global__ void __launch_bounds__(256) filter_kernel(const float* __restrict__ sino) {
    __shared__ float sre[512];
    __shared__ float sim[512];
    __shared__ float twr[256];
    __shared__ float twi[256];

    int tid = threadIdx.x;
    int base = blockIdx.x * 2 * NC;

    twr[tid] = g_twr[tid];
    twi[tid] = g_twi[tid];
    sre[tid]       = sino[base + tid];
    sre[tid + 256] = sino[base + tid + 256];
    sim[tid]       = sino[base + NC + tid];
    sim[tid + 256] = sino[base + NC + tid + 256];
    __syncthreads();

    // DIF forward
    {
        int step = 1;
        for (int len = 512; len >= 2; len >>= 1, step <<= 1) {
            int half = len >> 1;
            int grp = tid / half;
            int j = tid - grp * half;
            int i0 = grp * len + j;
            int i1 = i0 + half;
            int tj = j * step;
            float wr = twr[tj], wi = twi[tj];
            float ar = sre[i0], ai = sim[i0];
            float br = sre[i1], bi = sim[i1];
            sre[i0] = ar + br;
            sim[i0] = ai + bi;
            float dr = ar - br, di = ai - bi;
            sre[i1] = dr * wr - di * wi;
            sim[i1] = dr * wi + di * wr;
            __syncthreads();
        }
    }

    // ramp multiply in bitrev slots (fold in 1/N of ifft)
    #pragma unroll
    for (int q = 0; q < 2; ++q) {
        int n = tid + q * 256;
        int f = (int)(__brev((unsigned)n) >> 23);
        int m = min(f, 512 - f);
        float scale = (float)m * (2.0f / (512.0f * 512.0f));
        sre[n] *= scale;
        sim[n] *= scale;
    }
    __syncthreads();

    // DIT inverse (conj twiddles)
    {
        int step = 256;
        for (int len = 2; len <= 512; len <<= 1, step >>= 1) {
            int half = len >> 1;
            int grp = tid / half;
            int j = tid - grp * half;
            int i0 = grp * len + j;
            int i1 = i0 + half;
            int tj = j * step;
            float wr = twr[tj], wi = -twi[tj];
            float ar = sre[i0], ai = sim[i0];
            float br = sre[i1], bi = sim[i1];
            float vr = br * wr - bi * wi;
            float vi = br * wi + bi * wr;
            sre[i0] = ar + vr;
            sim[i0] = ai + vi;
            sre[i1] = ar - vr;
            sim[i1] = ai - vi;
            __syncthreads();
        }
    }

    // sre = filtered even row, sim = filtered odd row of this pair
    int pb = blockIdx.x * NC;
    g_pack[pb + tid]       = __floats2half2_rn(sre[tid], sim[tid]);
    g_pack[pb + tid + 256] = __floats2half2_rn(sre[tid + 256], sim[tid + 256]);
}

#define TILE  32
#define WIN   52
#define NPAIR 4   // 4 image-pairs = 8 images per block
#define NRP   (NR / 2)

// Block: 16x16 threads, 32x32 tile (2x2 px/thread), 8 images, 2 views/stage.
// sp[u][k][off] = (pack[w0+off], pack[w0+off+1]) -> one LDS.64 yields both
// bilinear taps for both images of pair k.
__global__ void __launch_bounds__(256) backproj_kernel(float* __restrict__ out) {
    __shared__ uint2 sp[2][NPAIR][WIN];
    __shared__ float scos[NV];
    __shared__ float ssin[NV];

    int tx = threadIdx.x;
    int ty = threadIdx.y;
    int tid = ty * 16 + tx;
    if (tid < NV) {
        scos[tid] = g_cosv[tid];
        ssin[tid] = g_sinv[tid];
    }

    int g    = blockIdx.z;         // 0..7
    int b    = g >> 2;
    int rblk = g & 3;
    int r0   = rblk * (2 * NPAIR); // first image index
    int rp0  = rblk * NPAIR;       // first pair index
    int x0   = blockIdx.x * TILE;
    int y0   = blockIdx.y * TILE;

    float xb = (float)(x0 + tx) - 255.5f;
    float yb = (float)(y0 + ty) - 255.5f;
    float xt = (float)x0 - 255.5f;
    float yt = (float)y0 - 255.5f;

    float2 acc[2][2][NPAIR];
    #pragma unroll
    for (int py = 0; py < 2; ++py)
        #pragma unroll
        for (int px = 0; px < 2; ++px)
            #pragma unroll
            for (int k = 0; k < NPAIR; ++k)
                acc[py][px][k] = make_float2(0.0f, 0.0f);

    const unsigned* packu = (const unsigned*)g_pack;
    const __half2 ones2 = __floats2half2_rn(1.0f, 1.0f);

    int srp = tid / WIN;            // staging pair index (0..4)
    int soff = tid - srp * WIN;     // staging offset
    bool stager = (tid < NPAIR * WIN);

    __syncthreads();   // scos/ssin visible

    for (int v = 0; v < NV; v += 2) {
        float c0 = scos[v],     s0 = ssin[v];
        float c1 = scos[v + 1], s1 = ssin[v + 1];

        float tmin0 = xt * c0 + yt * s0 + 255.5f + fminf(31.0f * c0, 0.0f) + fminf(31.0f * s0, 0.0f);
        float tmin1 = xt * c1 + yt * s1 + 255.5f + fminf(31.0f * c1, 0.0f) + fminf(31.0f * s1, 0.0f);
        int w0 = max(0, min((int)floorf(tmin0) - 1, 465));
        int w1 = max(0, min((int)floorf(tmin1) - 1, 465));

        __syncthreads();   // previous iteration's readers done

        if (stager) {
            {
                int rowb = ((b * NV + v) * NRP + rp0 + srp) * NC;
                int gi = w0 + soff;
                unsigned p0 = packu[rowb + min(gi, 511)];
                unsigned p1 = packu[rowb + min(gi + 1, 511)];
                sp[0][srp][soff] = make_uint2(p0, p1);
            }
            {
                int rowb = ((b * NV + v + 1) * NRP + rp0 + srp) * NC;
                int gi = w1 + soff;
                unsigned p0 = packu[rowb + min(gi, 511)];
                unsigned p1 = packu[rowb + min(gi + 1, 511)];
                sp[1][srp][soff] = make_uint2(p0, p1);
            }
        }
        __syncthreads();

        float t000 = fmaf(xb, c0, fmaf(yb, s0, 255.5f));
        float t001 = fmaf(xb, c1, fmaf(yb, s1, 255.5f));
        float c160 = 16.0f * c0, s160 = 16.0f * s0;
        float c161 = 16.0f * c1, s161 = 16.0f * s1;

        #pragma unroll
        for (int py = 0; py < 2; ++py) {
            #pragma unroll
            for (int px = 0; px < 2; ++px) {
                // view v
                float ta = t000 + (float)px * c160 + (float)py * s160;
                ta = fminf(fmaxf(ta, 0.0f), 511.0f);
                int ia = __float2int_rd(ta);
                float wa = ta - (float)ia;
                int la = ia - w0;
                __half2 wab  = __float2half2_rn(wa);
                __half2 wab1 = __hsub2(ones2, wab);
                // view v+1
                float tb = t001 + (float)px * c161 + (float)py * s161;
                tb = fminf(fmaxf(tb, 0.0f), 511.0f);
                int ib = __float2int_rd(tb);
                float wb = tb - (float)ib;
                int lb = ib - w1;
                __half2 wbb  = __float2half2_rn(wb);
                __half2 wbb1 = __hsub2(ones2, wbb);

                #pragma unroll
                for (int k = 0; k < NPAIR; ++k) {
                    uint2 qa = sp[0][k][la];
                    uint2 qb = sp[1][k][lb];
                    __half2 loa = *(__half2*)&qa.x;
                    __half2 hia = *(__half2*)&qa.y;
                    __half2 lob = *(__half2*)&qb.x;
                    __half2 hib = *(__half2*)&qb.y;
                    __half2 vv;
                    vv = __hmul2(loa, wab1);
                    vv = __hfma2(hia, wab, vv);
                    vv = __hfma2(lob, wbb1, vv);
                    vv = __hfma2(hib, wbb, vv);
                    float2 vf = __half22float2(vv);
                    acc[py][px][k].x += vf.x;
                    acc[py][px][k].y += vf.y;
                }
            }
        }
    }

    const float outscale = (float)(PI_D / (double)NV);
    #pragma unroll
    for (int k = 0; k < NPAIR; ++k) {
        #pragma unroll
        for (int py = 0; py < 2; ++py) {
            #pragma unroll
            for (int px = 0; px < 2; ++px) {
                int y = y0 + ty + py * 16;
                int x = x0 + tx + px * 16;
                int imgA = r0 + 2 * k;
                float va = fmaxf(acc[py][px][k].x * outscale, 0.0f);
                float vb = fmaxf(acc[py][px][k].y * outscale, 0.0f);
                out[(((b * NR + imgA) * NPIX) + y) * NPIX + x] = va;
                out[(((b * NR + imgA + 1) * NPIX) + y) * NPIX + x] = vb;
            }
        }
    }
}

extern "C" void kernel_launch(void* const* d_in, const int* in_sizes, int n_in,
                              void* d_out, int out_size) {
    const float* sino = (const float*)d_in[0];
    float* out = (float*)d_out;
    (void)in_sizes; (void)n_in; (void)out_size;

    init_tables_kernel<<<1, 256>>>();
    filter_kernel<<<NB * NV * NR / 2, 256>>>(sino);
    dim3 bpGrid(NPIX / TILE, NPIX / TILE, (NB * NR) / (2 * NPAIR));
    dim3 bpBlock(16, 16);
    backproj_kernel<<<bpGrid, bpBlock>>>(out);
}

// round 3
// speedup vs baseline: 1.7190x; 1.0656x over previous
#include <cuda_runtime.h>
#include <cuda_fp16.h>
#include <math.h>

#define NB 2
#define NV 180
#define NR 32
#define NC 512
#define NPIX 512
#define PI_D 3.14159265358979323846

#define NRP (NR / 2)

// Filtered sinogram, image-pair packed: g_pack[((b*NV+v)*NRP+rp)*NC + i]
//   = half2( filt[b,v,2rp,i], filt[b,v,2rp+1,i] )
__device__ __half2 g_pack[NB * NV * NRP * NC + 4];
__device__ float g_twr[256];
__device__ float g_twi[256];
__device__ float g_cosv[NV];
__device__ float g_sinv[NV];

__global__ void init_tables_kernel() {
    int i = threadIdx.x;
    if (i < 256) {
        double a = -2.0 * PI_D * (double)i / 512.0;
        g_twr[i] = (float)cos(a);
        g_twi[i] = (float)sin(a);
    }
    if (i < NV) {
        double th = (double)i * PI_D / (double)NV;
        g_cosv[i] = (float)cos(th);
        g_sinv[i] = (float)sin(th);
    }
}

// One block filters TWO consecutive real rows packed as one complex 512-pt FFT.
// DIF forward -> ramp in bit-reversed slots -> DIT inverse (conj twiddles).
// Stages with len<=64 are warp-local -> __syncwarp only.
__global__ void __launch_bounds__(256) filter_kernel(const float* __restrict__ sino) {
    __shared__ float sre[512];
    __shared__ float sim[512];
    __shared__ float twr[256];
    __shared__ float twi[256];

    int tid = threadIdx.x;
    int base = blockIdx.x * 2 * NC;

    twr[tid] = g_twr[tid];
    twi[tid] = g_twi[tid];
    sre[tid]       = sino[base + tid];
    sre[tid + 256] = sino[base + tid + 256];
    sim[tid]       = sino[base + NC + tid];
    sim[tid + 256] = sino[base + NC + tid + 256];
    __syncthreads();

    // ---- DIF forward ----
    {
        int step = 1;
        for (int len = 512; len >= 2; len >>= 1, step <<= 1) {
            int half = len >> 1;
            int grp = tid / half;
            int j = tid - grp * half;
            int i0 = grp * len + j;
            int i1 = i0 + half;
            int tj = j * step;
            float wr = twr[tj], wi = twi[tj];
            float ar = sre[i0], ai = sim[i0];
            float br = sre[i1], bi = sim[i1];
            sre[i0] = ar + br;
            sim[i0] = ai + bi;
            float dr = ar - br, di = ai - bi;
            sre[i1] = dr * wr - di * wi;
            sim[i1] = dr * wi + di * wr;
            if (len > 128) __syncthreads();
            else if (len == 128) __syncthreads();
            else __syncwarp();
        }
    }

    // ---- ramp multiply in bitrev slots (warp-local elements 2t, 2t+1) ----
    #pragma unroll
    for (int q = 0; q < 2; ++q) {
        int n = 2 * tid + q;
        int f = (int)(__brev((unsigned)n) >> 23);
        int m = min(f, 512 - f);
        float scale = (float)m * (2.0f / (512.0f * 512.0f));
        sre[n] *= scale;
        sim[n] *= scale;
    }
    __syncwarp();

    // ---- DIT inverse (conj twiddles) ----
    {
        int step = 256;
        for (int len = 2; len <= 512; len <<= 1, step >>= 1) {
            int half = len >> 1;
            int grp = tid / half;
            int j = tid - grp * half;
            int i0 = grp * len + j;
            int i1 = i0 + half;
            int tj = j * step;
            float wr = twr[tj], wi = -twi[tj];
            float ar = sre[i0], ai = sim[i0];
            float br = sre[i1], bi = sim[i1];
            float vr = br * wr - bi * wi;
            float vi = br * wi + bi * wr;
            sre[i0] = ar + vr;
            sim[i0] = ai + vi;
            sre[i1] = ar - vr;
            sim[i1] = ai - vi;
            if (len >= 64) __syncthreads();
            else __syncwarp();
        }
    }

    int pb = blockIdx.x * NC;
    g_pack[pb + tid]       = __floats2half2_rn(sre[tid], sim[tid]);
    g_pack[pb + tid + 256] = __floats2half2_rn(sre[tid + 256], sim[tid + 256]);
}

#define TILE  32
#define WIN   52
#define NPAIR 8   // 8 image-pairs = 16 images per block

// Block: 16x16 threads, 32x32 tile (2x2 px/thread), 16 images,
// 2 views per stage, double-buffered staging (1 barrier per iter).
__global__ void __launch_bounds__(256, 2) backproj_kernel(float* __restrict__ out) {
    __shared__ uint2 sp[2][2][NPAIR][WIN];
    __shared__ float scos[NV];
    __shared__ float ssin[NV];

    int tx = threadIdx.x;
    int ty = threadIdx.y;
    int tid = ty * 16 + tx;
    if (tid < NV) {
        scos[tid] = g_cosv[tid];
        ssin[tid] = g_sinv[tid];
    }
    __syncthreads();

    int g    = blockIdx.z;      // 0..3
    int b    = g >> 1;
    int rblk = g & 1;
    int r0   = rblk * (2 * NPAIR);
    int rp0  = rblk * NPAIR;
    int x0   = blockIdx.x * TILE;
    int y0   = blockIdx.y * TILE;

    float xb = (float)(x0 + tx) - 255.5f;
    float yb = (float)(y0 + ty) - 255.5f;
    float xt = (float)x0 - 255.5f;
    float yt = (float)y0 - 255.5f;

    // staging assignment: 416 entries per view, 2 per thread
    int e1 = tid + 256;
    int srpa = tid / WIN, soffa = tid - srpa * WIN;
    int srpb = e1 / WIN,  soffb = e1 - srpb * WIN;
    bool haveb = (e1 < NPAIR * WIN);

    const unsigned* packu = (const unsigned*)g_pack;
    int vrow0 = (b * NV) * NRP + rp0;   // row(v, srp) = vrow0 + v*NRP + srp

    unsigned long long acc[2][2][NPAIR];
    #pragma unroll
    for (int py = 0; py < 2; ++py)
        #pragma unroll
        for (int px = 0; px < 2; ++px)
            #pragma unroll
            for (int k = 0; k < NPAIR; ++k)
                acc[py][px][k] = 0ull;

    const __half2 ones2 = __floats2half2_rn(1.0f, 1.0f);

    auto window = [&](float c, float s) -> int {
        float tmin = xt * c + yt * s + 255.5f
                   + fminf(31.0f * c, 0.0f) + fminf(31.0f * s, 0.0f);
        int w = (int)floorf(tmin) - 1;
        return max(0, min(w, 465));
    };

    auto stage = [&](int buf, int v, int wa, int wb) {
        int rb0 = (vrow0 + v * NRP) * NC;
        int rb1 = rb0 + NRP * NC;
        {
            int row = rb0 + srpa * NC;
            int gi = wa + soffa;
            sp[buf][0][srpa][soffa] =
                make_uint2(packu[row + min(gi, 511)], packu[row + min(gi + 1, 511)]);
        }
        {
            int row = rb1 + srpa * NC;
            int gi = wb + soffa;
            sp[buf][1][srpa][soffa] =
                make_uint2(packu[row + min(gi, 511)], packu[row + min(gi + 1, 511)]);
        }
        if (haveb) {
            int row = rb0 + srpb * NC;
            int gi = wa + soffb;
            sp[buf][0][srpb][soffb] =
                make_uint2(packu[row + min(gi, 511)], packu[row + min(gi + 1, 511)]);
            row = rb1 + srpb * NC;
            gi = wb + soffb;
            sp[buf][1][srpb][soffb] =
                make_uint2(packu[row + min(gi, 511)], packu[row + min(gi + 1, 511)]);
        }
    };

    // current view-pair params
    float c0 = scos[0], s0 = ssin[0];
    float c1 = scos[1], s1 = ssin[1];
    int w0 = window(c0, s0);
    int w1 = window(c1, s1);
    stage(0, 0, w0, w1);
    __syncthreads();

    for (int it = 0; it < NV / 2; ++it) {
        int buf = it & 1;

        float nc0, ns0, nc1, ns1;
        int nw0 = 0, nw1 = 0;
        bool more = (it < NV / 2 - 1);
        if (more) {
            int v = 2 * it + 2;
            nc0 = scos[v];     ns0 = ssin[v];
            nc1 = scos[v + 1]; ns1 = ssin[v + 1];
            nw0 = window(nc0, ns0);
            nw1 = window(nc1, ns1);
            stage(buf ^ 1, v, nw0, nw1);
        }

        // compute from sp[buf] with current c/s/w
        float t000 = fmaf(xb, c0, fmaf(yb, s0, 255.5f));
        float t001 = fmaf(xb, c1, fmaf(yb, s1, 255.5f));
        float c160 = 16.0f * c0, s160 = 16.0f * s0;
        float c161 = 16.0f * c1, s161 = 16.0f * s1;

        #pragma unroll
        for (int py = 0; py < 2; ++py) {
            #pragma unroll
            for (int px = 0; px < 2; ++px) {
                float ta = t000 + (float)px * c160 + (float)py * s160;
                ta = fminf(fmaxf(ta, 0.0f), 511.0f);
                int ia = __float2int_rd(ta);
                float wa = ta - (float)ia;
                int la = ia - w0;
                __half2 wab  = __float2half2_rn(wa);
                __half2 wab1 = __hsub2(ones2, wab);

                float tb = t001 + (float)px * c161 + (float)py * s161;
                tb = fminf(fmaxf(tb, 0.0f), 511.0f);
                int ib = __float2int_rd(tb);
                float wb = tb - (float)ib;
                int lb = ib - w1;
                __half2 wbb  = __float2half2_rn(wb);
                __half2 wbb1 = __hsub2(ones2, wbb);

                #pragma unroll
                for (int k = 0; k < NPAIR; ++k) {
                    uint2 qa = sp[buf][0][k][la];
                    uint2 qb = sp[buf][1][k][lb];
                    __half2 loa = *(__half2*)&qa.x;
                    __half2 hia = *(__half2*)&qa.y;
                    __half2 lob = *(__half2*)&qb.x;
                    __half2 hib = *(__half2*)&qb.y;
                    __half2 vv;
                    vv = __hmul2(loa, wab1);
                    vv = __hfma2(hia, wab, vv);
                    vv = __hfma2(lob, wbb1, vv);
                    vv = __hfma2(hib, wbb, vv);
                    float2 vf = __half22float2(vv);
                    unsigned long long vp;
                    asm("mov.b64 %0, {%1, %2};" : "=l"(vp) : "f"(vf.x), "f"(vf.y));
                    asm("add.rn.f32x2 %0, %0, %1;" : "+l"(acc[py][px][k]) : "l"(vp));
                }
            }
        }

        __syncthreads();

        if (more) {
            c0 = nc0; s0 = ns0; c1 = nc1; s1 = ns1;
            w0 = nw0; w1 = nw1;
        }
    }

    const float outscale = (float)(PI_D / (double)NV);
    #pragma unroll
    for (int k = 0; k < NPAIR; ++k) {
        #pragma unroll
        for (int py = 0; py < 2; ++py) {
            #pragma unroll
            for (int px = 0; px < 2; ++px) {
                int y = y0 + ty + py * 16;
                int x = x0 + tx + px * 16;
                int imgA = r0 + 2 * k;
                float ax, ay;
                asm("mov.b64 {%0, %1}, %2;" : "=f"(ax), "=f"(ay) : "l"(acc[py][px][k]));
                float va = fmaxf(ax * outscale, 0.0f);
                float vb = fmaxf(ay * outscale, 0.0f);
                out[(((b * NR + imgA) * NPIX) + y) * NPIX + x] = va;
                out[(((b * NR + imgA + 1) * NPIX) + y) * NPIX + x] = vb;
            }
        }
    }
}

extern "C" void kernel_launch(void* const* d_in, const int* in_sizes, int n_in,
                              void* d_out, int out_size) {
    const float* sino = (const float*)d_in[0];
    float* out = (float*)d_out;
    (void)in_sizes; (void)n_in; (void)out_size;

    init_tables_kernel<<<1, 256>>>();
    filter_kernel<<<NB * NV * NR / 2, 256>>>(sino);
    dim3 bpGrid(NPIX / TILE, NPIX / TILE, (NB * NR) / (2 * NPAIR));
    dim3 bpBlock(16, 16);
    backproj_kernel<<<bpGrid, bpBlock>>>(out);
}

// round 7
// speedup vs baseline: 1.7354x; 1.0095x over previous
#include <cuda_runtime.h>
#include <cuda_fp16.h>
#include <math.h>

#define NB 2
#define NV 180
#define NR 32
#define NC 512
#define NPIX 512
#define PI_D 3.14159265358979323846

#define NRP (NR / 2)

// Filtered sinogram, image-pair packed: g_pack[((b*NV+v)*NRP+rp)*NC + i]
//   = half2( filt[b,v,2rp,i], filt[b,v,2rp+1,i] )
__device__ __half2 g_pack[NB * NV * NRP * NC + 4];

// One block filters TWO consecutive real rows packed as one complex 512-pt FFT.
// DIF forward -> ramp in bit-reversed slots -> DIT inverse (conj twiddles).
// Twiddles computed in-block via sincospif (no init kernel).
__global__ void __launch_bounds__(256) filter_kernel(const float* __restrict__ sino) {
    __shared__ float sre[512];
    __shared__ float sim[512];
    __shared__ float twr[256];
    __shared__ float twi[256];

    int tid = threadIdx.x;
    int base = blockIdx.x * 2 * NC;

    {
        float s, c;
        sincospif(-(float)tid * (1.0f / 256.0f), &s, &c);  // exp(-2*pi*i*tid/512)
        twr[tid] = c;
        twi[tid] = s;
    }
    sre[tid]       = sino[base + tid];
    sre[tid + 256] = sino[base + tid + 256];
    sim[tid]       = sino[base + NC + tid];
    sim[tid + 256] = sino[base + NC + tid + 256];
    __syncthreads();

    // ---- DIF forward ----
    {
        int step = 1;
        for (int len = 512; len >= 2; len >>= 1, step <<= 1) {
            int half = len >> 1;
            int grp = tid / half;
            int j = tid - grp * half;
            int i0 = grp * len + j;
            int i1 = i0 + half;
            int tj = j * step;
            float wr = twr[tj], wi = twi[tj];
            float ar = sre[i0], ai = sim[i0];
            float br = sre[i1], bi = sim[i1];
            sre[i0] = ar + br;
            sim[i0] = ai + bi;
            float dr = ar - br, di = ai - bi;
            sre[i1] = dr * wr - di * wi;
            sim[i1] = dr * wi + di * wr;
            if (len >= 128) __syncthreads();
            else __syncwarp();
        }
    }

    // ---- ramp multiply in bitrev slots (warp-local elements 2t, 2t+1) ----
    #pragma unroll
    for (int q = 0; q < 2; ++q) {
        int n = 2 * tid + q;
        int f = (int)(__brev((unsigned)n) >> 23);
        int m = min(f, 512 - f);
        float scale = (float)m * (2.0f / (512.0f * 512.0f));
        sre[n] *= scale;
        sim[n] *= scale;
    }
    __syncwarp();

    // ---- DIT inverse (conj twiddles) ----
    {
        int step = 256;
        for (int len = 2; len <= 512; len <<= 1, step >>= 1) {
            int half = len >> 1;
            int grp = tid / half;
            int j = tid - grp * half;
            int i0 = grp * len + j;
            int i1 = i0 + half;
            int tj = j * step;
            float wr = twr[tj], wi = -twi[tj];
            float ar = sre[i0], ai = sim[i0];
            float br = sre[i1], bi = sim[i1];
            float vr = br * wr - bi * wi;
            float vi = br * wi + bi * wr;
            sre[i0] = ar + vr;
            sim[i0] = ai + vi;
            sre[i1] = ar - vr;
            sim[i1] = ai - vi;
            if (len >= 64) __syncthreads();
            else __syncwarp();
        }
    }

    int pb = blockIdx.x * NC;
    g_pack[pb + tid]       = __floats2half2_rn(sre[tid], sim[tid]);
    g_pack[pb + tid + 256] = __floats2half2_rn(sre[tid + 256], sim[tid + 256]);
}

#define TILE  32
#define WIN   52
#define NPAIR 8   // 8 image-pairs = 16 images per block

// Block: 256 threads (1-D!), 32x32 tile (2x2 px/thread), 16 images,
// 2 views per stage, double-buffered staging.
// Warp footprint remapped to 8x4 threads so per-warp t-span fits in one
// 128B smem wavefront per LDS.64 (7|c|+3|s|+1 slots <= ~9 * 8B = 72B).
__global__ void __launch_bounds__(256, 2) backproj_kernel(float* __restrict__ out) {
    __shared__ uint2 sp[2][2][NPAIR][WIN];
    __shared__ float scos[NV];
    __shared__ float ssin[NV];

    int tid = threadIdx.x;   // 0..255 (1-D launch)
    if (tid < NV) {
        float s, c;
        sincospif((float)tid * (1.0f / (float)NV), &s, &c);
        scos[tid] = c;
        ssin[tid] = s;
    }
    __syncthreads();

    // 8x4 warp footprint: warps tiled 2 wide x 4 tall over the 16x16 grid
    int lane = tid & 31;
    int w    = tid >> 5;
    int tx = ((w & 1) << 3) | (lane & 7);   // 0..15
    int ty = ((w >> 1) << 2) | (lane >> 3); // 0..15

    int g    = blockIdx.z;      // 0..3
    int b    = g >> 1;
    int rblk = g & 1;
    int r0   = rblk * (2 * NPAIR);
    int rp0  = rblk * NPAIR;
    int x0   = blockIdx.x * TILE;
    int y0   = blockIdx.y * TILE;

    float xb = (float)(x0 + tx) - 255.5f;
    float yb = (float)(y0 + ty) - 255.5f;
    float xt = (float)x0 - 255.5f;
    float yt = (float)y0 - 255.5f;

    // staging assignment: 416 entries per view, 2 per thread
    int e1 = tid + 256;
    int srpa = tid / WIN, soffa = tid - srpa * WIN;
    int srpb = e1 / WIN,  soffb = e1 - srpb * WIN;
    bool haveb = (e1 < NPAIR * WIN);

    const unsigned* packu = (const unsigned*)g_pack;
    int vrow0 = (b * NV) * NRP + rp0;

    unsigned long long acc[2][2][NPAIR];
    #pragma unroll
    for (int py = 0; py < 2; ++py)
        #pragma unroll
        for (int px = 0; px < 2; ++px)
            #pragma unroll
            for (int k = 0; k < NPAIR; ++k)
                acc[py][px][k] = 0ull;

    const __half2 ones2 = __floats2half2_rn(1.0f, 1.0f);

    auto window = [&](float c, float s) -> int {
        float tmin = xt * c + yt * s + 255.5f
                   + fminf(31.0f * c, 0.0f) + fminf(31.0f * s, 0.0f);
        int wv = (int)floorf(tmin) - 1;
        return max(0, min(wv, 465));
    };

    auto stage = [&](int buf, int v, int wa, int wb) {
        int rb0 = (vrow0 + v * NRP) * NC;
        int rb1 = rb0 + NRP * NC;
        {
            int row = rb0 + srpa * NC;
            int gi = wa + soffa;
            sp[buf][0][srpa][soffa] =
                make_uint2(packu[row + min(gi, 511)], packu[row + min(gi + 1, 511)]);
        }
        {
            int row = rb1 + srpa * NC;
            int gi = wb + soffa;
            sp[buf][1][srpa][soffa] =
                make_uint2(packu[row + min(gi, 511)], packu[row + min(gi + 1, 511)]);
        }
        if (haveb) {
            int row = rb0 + srpb * NC;
            int gi = wa + soffb;
            sp[buf][0][srpb][soffb] =
                make_uint2(packu[row + min(gi, 511)], packu[row + min(gi + 1, 511)]);
            row = rb1 + srpb * NC;
            gi = wb + soffb;
            sp[buf][1][srpb][soffb] =
                make_uint2(packu[row + min(gi, 511)], packu[row + min(gi + 1, 511)]);
        }
    };

    float c0 = scos[0], s0 = ssin[0];
    float c1 = scos[1], s1 = ssin[1];
    int w0 = window(c0, s0);
    int w1 = window(c1, s1);
    stage(0, 0, w0, w1);
    __syncthreads();

    for (int it = 0; it < NV / 2; ++it) {
        int buf = it & 1;

        float nc0, ns0, nc1, ns1;
        int nw0 = 0, nw1 = 0;
        bool more = (it < NV / 2 - 1);
        if (more) {
            int v = 2 * it + 2;
            nc0 = scos[v];     ns0 = ssin[v];
            nc1 = scos[v + 1]; ns1 = ssin[v + 1];
            nw0 = window(nc0, ns0);
            nw1 = window(nc1, ns1);
            stage(buf ^ 1, v, nw0, nw1);
        }

        float t000 = fmaf(xb, c0, fmaf(yb, s0, 255.5f));
        float t001 = fmaf(xb, c1, fmaf(yb, s1, 255.5f));
        float c160 = 16.0f * c0, s160 = 16.0f * s0;
        float c161 = 16.0f * c1, s161 = 16.0f * s1;

        #pragma unroll
        for (int py = 0; py < 2; ++py) {
            #pragma unroll
            for (int px = 0; px < 2; ++px) {
                float ta = t000 + (float)px * c160 + (float)py * s160;
                ta = fminf(fmaxf(ta, 0.0f), 511.0f);
                int ia = __float2int_rd(ta);
                float wa = ta - (float)ia;
                int la = ia - w0;
                __half2 wab  = __float2half2_rn(wa);
                __half2 wab1 = __hsub2(ones2, wab);

                float tb = t001 + (float)px * c161 + (float)py * s161;
                tb = fminf(fmaxf(tb, 0.0f), 511.0f);
                int ib = __float2int_rd(tb);
                float wb = tb - (float)ib;
                int lb = ib - w1;
                __half2 wbb  = __float2half2_rn(wb);
                __half2 wbb1 = __hsub2(ones2, wbb);

                #pragma unroll
                for (int k = 0; k < NPAIR; ++k) {
                    uint2 qa = sp[buf][0][k][la];
                    uint2 qb = sp[buf][1][k][lb];
                    __half2 loa = *(__half2*)&qa.x;
                    __half2 hia = *(__half2*)&qa.y;
                    __half2 lob = *(__half2*)&qb.x;
                    __half2 hib = *(__half2*)&qb.y;
                    __half2 vv;
                    vv = __hmul2(loa, wab1);
                    vv = __hfma2(hia, wab, vv);
                    vv = __hfma2(lob, wbb1, vv);
                    vv = __hfma2(hib, wbb, vv);
                    float2 vf = __half22float2(vv);
                    unsigned long long vp;
                    asm("mov.b64 %0, {%1, %2};" : "=l"(vp) : "f"(vf.x), "f"(vf.y));
                    asm("add.rn.f32x2 %0, %0, %1;" : "+l"(acc[py][px][k]) : "l"(vp));
                }
            }
        }

        __syncthreads();

        if (more) {
            c0 = nc0; s0 = ns0; c1 = nc1; s1 = ns1;
            w0 = nw0; w1 = nw1;
        }
    }

    const float outscale = (float)(PI_D / (double)NV);
    #pragma unroll
    for (int k = 0; k < NPAIR; ++k) {
        #pragma unroll
        for (int py = 0; py < 2; ++py) {
            #pragma unroll
            for (int px = 0; px < 2; ++px) {
                int y = y0 + ty + py * 16;
                int x = x0 + tx + px * 16;
                int imgA = r0 + 2 * k;
                float ax, ay;
                asm("mov.b64 {%0, %1}, %2;" : "=f"(ax), "=f"(ay) : "l"(acc[py][px][k]));
                float va = fmaxf(ax * outscale, 0.0f);
                float vb = fmaxf(ay * outscale, 0.0f);
                out[(((b * NR + imgA) * NPIX) + y) * NPIX + x] = va;
                out[(((b * NR + imgA + 1) * NPIX) + y) * NPIX + x] = vb;
            }
        }
    }
}

extern "C" void kernel_launch(void* const* d_in, const int* in_sizes, int n_in,
                              void* d_out, int out_size) {
    const float* sino = (const float*)d_in[0];
    float* out = (float*)d_out;
    (void)in_sizes; (void)n_in; (void)out_size;

    filter_kernel<<<NB * NV * NR / 2, 256>>>(sino);
    dim3 bpGrid(NPIX / TILE, NPIX / TILE, (NB * NR) / (2 * NPAIR));
    backproj_kernel<<<bpGrid, 256>>>(out);   // 1-D 256-thread block
}

// round 8
// speedup vs baseline: 1.7896x; 1.0312x over previous
#include <cuda_runtime.h>
#include <cuda_fp16.h>
#include <math.h>

#define NB 2
#define NV 180
#define NR 32
#define NC 512
#define NPIX 512
#define PI_D 3.14159265358979323846

#define NRP (NR / 2)

// Filtered sinogram, image-pair packed: g_pack[((b*NV+v)*NRP+rp)*NC + i]
//   = half2( filt[b,v,2rp,i], filt[b,v,2rp+1,i] )
__device__ __half2 g_pack[NB * NV * NRP * NC + 4];

// One block filters TWO consecutive real rows packed as one complex 512-pt FFT.
__global__ void __launch_bounds__(256) filter_kernel(const float* __restrict__ sino) {
    __shared__ float sre[512];
    __shared__ float sim[512];
    __shared__ float twr[256];
    __shared__ float twi[256];

    int tid = threadIdx.x;
    int base = blockIdx.x * 2 * NC;

    {
        float s, c;
        sincospif(-(float)tid * (1.0f / 256.0f), &s, &c);  // exp(-2*pi*i*tid/512)
        twr[tid] = c;
        twi[tid] = s;
    }
    sre[tid]       = sino[base + tid];
    sre[tid + 256] = sino[base + tid + 256];
    sim[tid]       = sino[base + NC + tid];
    sim[tid + 256] = sino[base + NC + tid + 256];
    __syncthreads();

    // ---- DIF forward ----
    {
        int step = 1;
        for (int len = 512; len >= 2; len >>= 1, step <<= 1) {
            int half = len >> 1;
            int grp = tid / half;
            int j = tid - grp * half;
            int i0 = grp * len + j;
            int i1 = i0 + half;
            int tj = j * step;
            float wr = twr[tj], wi = twi[tj];
            float ar = sre[i0], ai = sim[i0];
            float br = sre[i1], bi = sim[i1];
            sre[i0] = ar + br;
            sim[i0] = ai + bi;
            float dr = ar - br, di = ai - bi;
            sre[i1] = dr * wr - di * wi;
            sim[i1] = dr * wi + di * wr;
            if (len >= 128) __syncthreads();
            else __syncwarp();
        }
    }

    // ---- ramp multiply in bitrev slots (warp-local elements 2t, 2t+1) ----
    #pragma unroll
    for (int q = 0; q < 2; ++q) {
        int n = 2 * tid + q;
        int f = (int)(__brev((unsigned)n) >> 23);
        int m = min(f, 512 - f);
        float scale = (float)m * (2.0f / (512.0f * 512.0f));
        sre[n] *= scale;
        sim[n] *= scale;
    }
    __syncwarp();

    // ---- DIT inverse (conj twiddles) ----
    {
        int step = 256;
        for (int len = 2; len <= 512; len <<= 1, step >>= 1) {
            int half = len >> 1;
            int grp = tid / half;
            int j = tid - grp * half;
            int i0 = grp * len + j;
            int i1 = i0 + half;
            int tj = j * step;
            float wr = twr[tj], wi = -twi[tj];
            float ar = sre[i0], ai = sim[i0];
            float br = sre[i1], bi = sim[i1];
            float vr = br * wr - bi * wi;
            float vi = br * wi + bi * wr;
            sre[i0] = ar + vr;
            sim[i0] = ai + vi;
            sre[i1] = ar - vr;
            sim[i1] = ai - vi;
            if (len >= 64) __syncthreads();
            else __syncwarp();
        }
    }

    int pb = blockIdx.x * NC;
    g_pack[pb + tid]       = __floats2half2_rn(sre[tid], sim[tid]);
    g_pack[pb + tid + 256] = __floats2half2_rn(sre[tid + 256], sim[tid + 256]);
}

#define TILE  32
#define WIN   52
#define NPAIR 8   // 8 image-pairs = 16 images per block
#define NKG   (NPAIR / 2)   // 4 pair-groups of 2 pairs

// Staged window layout: sp[buf][view][loc][kg] : uint4 =
//   ( pairA.lo, pairA.hi, pairB.lo, pairB.hi ) for pairs (2kg, 2kg+1).
// One LDS.128 yields both bilinear taps for 2 pairs (4 samples per view).
// Per-loc stride padded to 5 uint4 (80B): bank stride 20 mod 32 ->
// same-bank aliasing only at dloc=8, beyond the 8x4 warp footprint span.
__global__ void __launch_bounds__(256, 2) backproj_kernel(float* __restrict__ out) {
    __shared__ uint4 sp[2][2][WIN][NKG + 1];
    __shared__ float scos[NV];
    __shared__ float ssin[NV];

    int tid = threadIdx.x;   // 0..255 (1-D launch)
    if (tid < NV) {
        float s, c;
        sincospif((float)tid * (1.0f / (float)NV), &s, &c);
        scos[tid] = c;
        ssin[tid] = s;
    }
    __syncthreads();

    // 8x4 warp footprint: warps tiled 2 wide x 4 tall over the 16x16 grid
    int lane = tid & 31;
    int w    = tid >> 5;
    int tx = ((w & 1) << 3) | (lane & 7);   // 0..15
    int ty = ((w >> 1) << 2) | (lane >> 3); // 0..15

    int g    = blockIdx.z;      // 0..3
    int b    = g >> 1;
    int rblk = g & 1;
    int r0   = rblk * (2 * NPAIR);
    int rp0  = rblk * NPAIR;
    int x0   = blockIdx.x * TILE;
    int y0   = blockIdx.y * TILE;

    float xb = (float)(x0 + tx) - 255.5f;
    float yb = (float)(y0 + ty) - 255.5f;
    float xt = (float)x0 - 255.5f;
    float yt = (float)y0 - 255.5f;

    // staging: 208 slots (kg, off), each thread handles both views of one slot
    int skg  = tid / WIN;            // 0..4 (valid < 4)
    int soff = tid - skg * WIN;
    bool stager = (tid < NKG * WIN);

    const unsigned* packu = (const unsigned*)g_pack;
    int vrow0 = (b * NV) * NRP + rp0;

    unsigned long long acc[2][2][NPAIR];
    #pragma unroll
    for (int py = 0; py < 2; ++py)
        #pragma unroll
        for (int px = 0; px < 2; ++px)
            #pragma unroll
            for (int k = 0; k < NPAIR; ++k)
                acc[py][px][k] = 0ull;

    const __half2 ones2 = __floats2half2_rn(1.0f, 1.0f);

    auto window = [&](float c, float s) -> int {
        float tmin = xt * c + yt * s + 255.5f
                   + fminf(31.0f * c, 0.0f) + fminf(31.0f * s, 0.0f);
        int wv = (int)floorf(tmin) - 1;
        return max(0, min(wv, 465));
    };

    // stage views v (window wa) and v+1 (window wb) into buffer buf
    auto stage = [&](int buf, int v, int wa, int wb) {
        if (!stager) return;
        int pA = (vrow0 + v * NRP + 2 * skg) * NC;       // pair 2*skg, view v
        int pB = pA + NC;                                 // pair 2*skg+1
        {
            int gi = wa + soff;
            int i0 = min(gi, 511), i1 = min(gi + 1, 511);
            uint4 q;
            q.x = packu[pA + i0];
            q.y = packu[pA + i1];
            q.z = packu[pB + i0];
            q.w = packu[pB + i1];
            sp[buf][0][soff][skg] = q;
        }
        {
            int pA1 = pA + NRP * NC;
            int pB1 = pB + NRP * NC;
            int gi = wb + soff;
            int i0 = min(gi, 511), i1 = min(gi + 1, 511);
            uint4 q;
            q.x = packu[pA1 + i0];
            q.y = packu[pA1 + i1];
            q.z = packu[pB1 + i0];
            q.w = packu[pB1 + i1];
            sp[buf][1][soff][skg] = q;
        }
    };

    float c0 = scos[0], s0 = ssin[0];
    float c1 = scos[1], s1 = ssin[1];
    int w0 = window(c0, s0);
    int w1 = window(c1, s1);
    stage(0, 0, w0, w1);
    __syncthreads();

    for (int it = 0; it < NV / 2; ++it) {
        int buf = it & 1;

        float nc0, ns0, nc1, ns1;
        int nw0 = 0, nw1 = 0;
        bool more = (it < NV / 2 - 1);
        if (more) {
            int v = 2 * it + 2;
            nc0 = scos[v];     ns0 = ssin[v];
            nc1 = scos[v + 1]; ns1 = ssin[v + 1];
            nw0 = window(nc0, ns0);
            nw1 = window(nc1, ns1);
            stage(buf ^ 1, v, nw0, nw1);
        }

        float t000 = fmaf(xb, c0, fmaf(yb, s0, 255.5f));
        float t001 = fmaf(xb, c1, fmaf(yb, s1, 255.5f));
        float c160 = 16.0f * c0, s160 = 16.0f * s0;
        float c161 = 16.0f * c1, s161 = 16.0f * s1;

        #pragma unroll
        for (int py = 0; py < 2; ++py) {
            #pragma unroll
            for (int px = 0; px < 2; ++px) {
                float ta = t000 + (float)px * c160 + (float)py * s160;
                ta = fminf(fmaxf(ta, 0.0f), 511.0f);
                int ia = __float2int_rd(ta);
                float wa = ta - (float)ia;
                int la = ia - w0;
                __half2 wab  = __float2half2_rn(wa);
                __half2 wab1 = __hsub2(ones2, wab);

                float tb = t001 + (float)px * c161 + (float)py * s161;
                tb = fminf(fmaxf(tb, 0.0f), 511.0f);
                int ib = __float2int_rd(tb);
                float wb = tb - (float)ib;
                int lb = ib - w1;
                __half2 wbb  = __float2half2_rn(wb);
                __half2 wbb1 = __hsub2(ones2, wbb);

                #pragma unroll
                for (int kg = 0; kg < NKG; ++kg) {
                    uint4 qa = sp[buf][0][la][kg];
                    uint4 qb = sp[buf][1][lb][kg];
                    // pair A = 2*kg
                    __half2 vA;
                    vA = __hmul2(*(__half2*)&qa.x, wab1);
                    vA = __hfma2(*(__half2*)&qa.y, wab, vA);
                    vA = __hfma2(*(__half2*)&qb.x, wbb1, vA);
                    vA = __hfma2(*(__half2*)&qb.y, wbb, vA);
                    float2 fA = __half22float2(vA);
                    unsigned long long vpA;
                    asm("mov.b64 %0, {%1, %2};" : "=l"(vpA) : "f"(fA.x), "f"(fA.y));
                    asm("add.rn.f32x2 %0, %0, %1;" : "+l"(acc[py][px][2 * kg]) : "l"(vpA));
                    // pair B = 2*kg+1
                    __half2 vB;
                    vB = __hmul2(*(__half2*)&qa.z, wab1);
                    vB = __hfma2(*(__half2*)&qa.w, wab, vB);
                    vB = __hfma2(*(__half2*)&qb.z, wbb1, vB);
                    vB = __hfma2(*(__half2*)&qb.w, wbb, vB);
                    float2 fB = __half22float2(vB);
                    unsigned long long vpB;
                    asm("mov.b64 %0, {%1, %2};" : "=l"(vpB) : "f"(fB.x), "f"(fB.y));
                    asm("add.rn.f32x2 %0, %0, %1;" : "+l"(acc[py][px][2 * kg + 1]) : "l"(vpB));
                }
            }
        }

        __syncthreads();

        if (more) {
            c0 = nc0; s0 = ns0; c1 = nc1; s1 = ns1;
            w0 = nw0; w1 = nw1;
        }
    }

    const float outscale = (float)(PI_D / (double)NV);
    #pragma unroll
    for (int k = 0; k < NPAIR; ++k) {
        #pragma unroll
        for (int py = 0; py < 2; ++py) {
            #pragma unroll
            for (int px = 0; px < 2; ++px) {
                int y = y0 + ty + py * 16;
                int x = x0 + tx + px * 16;
                int imgA = r0 + 2 * k;
                float ax, ay;
                asm("mov.b64 {%0, %1}, %2;" : "=f"(ax), "=f"(ay) : "l"(acc[py][px][k]));
                float va = fmaxf(ax * outscale, 0.0f);
                float vb = fmaxf(ay * outscale, 0.0f);
                out[(((b * NR + imgA) * NPIX) + y) * NPIX + x] = va;
                out[(((b * NR + imgA + 1) * NPIX) + y) * NPIX + x] = vb;
            }
        }
    }
}

extern "C" void kernel_launch(void* const* d_in, const int* in_sizes, int n_in,
                              void* d_out, int out_size) {
    const float* sino = (const float*)d_in[0];
    float* out = (float*)d_out;
    (void)in_sizes; (void)n_in; (void)out_size;

    filter_kernel<<<NB * NV * NR / 2, 256>>>(sino);
    dim3 bpGrid(NPIX / TILE, NPIX / TILE, (NB * NR) / (2 * NPAIR));
    backproj_kernel<<<bpGrid, 256>>>(out);   // 1-D 256-thread block
}

// round 9
// speedup vs baseline: 1.8542x; 1.0361x over previous
#include <cuda_runtime.h>
#include <cuda_fp16.h>
#include <math.h>

#define NB 2
#define NV 180
#define NR 32
#define NC 512
#define NPIX 512
#define PI_D 3.14159265358979323846

#define NRP (NR / 2)

// Filtered sinogram, image-pair packed: g_pack[((b*NV+v)*NRP+rp)*NC + i]
//   = half2( filt[b,v,2rp,i], filt[b,v,2rp+1,i] )
// +16 pad: staging reads overrun a row by up to 6 entries (never consumed).
__device__ __half2 g_pack[NB * NV * NRP * NC + 16];

// One block filters TWO consecutive real rows packed as one complex 512-pt FFT.
__global__ void __launch_bounds__(256) filter_kernel(const float* __restrict__ sino) {
    __shared__ float sre[512];
    __shared__ float sim[512];
    __shared__ float twr[256];
    __shared__ float twi[256];

    int tid = threadIdx.x;
    int base = blockIdx.x * 2 * NC;

    {
        float s, c;
        sincospif(-(float)tid * (1.0f / 256.0f), &s, &c);  // exp(-2*pi*i*tid/512)
        twr[tid] = c;
        twi[tid] = s;
    }
    sre[tid]       = sino[base + tid];
    sre[tid + 256] = sino[base + tid + 256];
    sim[tid]       = sino[base + NC + tid];
    sim[tid + 256] = sino[base + NC + tid + 256];
    __syncthreads();

    // ---- DIF forward ----
    {
        int step = 1;
        for (int len = 512; len >= 2; len >>= 1, step <<= 1) {
            int half = len >> 1;
            int grp = tid / half;
            int j = tid - grp * half;
            int i0 = grp * len + j;
            int i1 = i0 + half;
            int tj = j * step;
            float wr = twr[tj], wi = twi[tj];
            float ar = sre[i0], ai = sim[i0];
            float br = sre[i1], bi = sim[i1];
            sre[i0] = ar + br;
            sim[i0] = ai + bi;
            float dr = ar - br, di = ai - bi;
            sre[i1] = dr * wr - di * wi;
            sim[i1] = dr * wi + di * wr;
            if (len >= 128) __syncthreads();
            else __syncwarp();
        }
    }

    // ---- ramp multiply in bitrev slots (warp-local elements 2t, 2t+1) ----
    #pragma unroll
    for (int q = 0; q < 2; ++q) {
        int n = 2 * tid + q;
        int f = (int)(__brev((unsigned)n) >> 23);
        int m = min(f, 512 - f);
        float scale = (float)m * (2.0f / (512.0f * 512.0f));
        sre[n] *= scale;
        sim[n] *= scale;
    }
    __syncwarp();

    // ---- DIT inverse (conj twiddles) ----
    {
        int step = 256;
        for (int len = 2; len <= 512; len <<= 1, step >>= 1) {
            int half = len >> 1;
            int grp = tid / half;
            int j = tid - grp * half;
            int i0 = grp * len + j;
            int i1 = i0 + half;
            int tj = j * step;
            float wr = twr[tj], wi = -twi[tj];
            float ar = sre[i0], ai = sim[i0];
            float br = sre[i1], bi = sim[i1];
            float vr = br * wr - bi * wi;
            float vi = br * wi + bi * wr;
            sre[i0] = ar + vr;
            sim[i0] = ai + vi;
            sre[i1] = ar - vr;
            sim[i1] = ai - vi;
            if (len >= 64) __syncthreads();
            else __syncwarp();
        }
    }

    int pb = blockIdx.x * NC;
    g_pack[pb + tid]       = __floats2half2_rn(sre[tid], sim[tid]);
    g_pack[pb + tid + 256] = __floats2half2_rn(sre[tid + 256], sim[tid + 256]);
}

#define TILE  32
#define WIN   52
#define NPAIR 8            // 8 image-pairs = 16 images per block
#define NKG   (NPAIR / 2)  // 4 pair-groups of 2 pairs
#define NBUF  4            // ring buffers (stage distance 2)

// sp[buf][view][loc][kg] : uint4 = (pairA.lo, pairA.hi, pairB.lo, pairB.hi).
// Per-loc stride padded to 5 uint4 (80B) -> bank stride 20 mod 32.
__global__ void __launch_bounds__(256, 2) backproj_kernel(float* __restrict__ out) {
    __shared__ uint4 sp[NBUF][2][WIN][NKG + 1];
    __shared__ float scos[NV];
    __shared__ float ssin[NV];
    __shared__ int   swin[NV];

    int tid = threadIdx.x;   // 0..255 (1-D launch)

    int g    = blockIdx.z;      // 0..3
    int b    = g >> 1;
    int rblk = g & 1;
    int r0   = rblk * (2 * NPAIR);
    int rp0  = rblk * NPAIR;
    int x0   = blockIdx.x * TILE;
    int y0   = blockIdx.y * TILE;

    float xt = (float)x0 - 255.5f;
    float yt = (float)y0 - 255.5f;

    // Precompute per-view cos/sin + staged-window start (block-uniform).
    if (tid < NV) {
        float s, c;
        sincospif((float)tid * (1.0f / (float)NV), &s, &c);
        scos[tid] = c;
        ssin[tid] = s;
        float tmin = xt * c + yt * s + 255.5f
                   + fminf(31.0f * c, 0.0f) + fminf(31.0f * s, 0.0f);
        int wv = (int)floorf(tmin) - 1;
        swin[tid] = max(0, min(wv, 465));
    }

    // 8x4 warp footprint: warps tiled 2 wide x 4 tall over the 16x16 grid
    int lane = tid & 31;
    int w    = tid >> 5;
    int tx = ((w & 1) << 3) | (lane & 7);   // 0..15
    int ty = ((w >> 1) << 2) | (lane >> 3); // 0..15

    float xb = (float)(x0 + tx) - 255.5f;
    float yb = (float)(y0 + ty) - 255.5f;

    // staging: 208 slots (kg, off); each thread handles both views of one slot
    int skg  = tid / WIN;            // 0..4 (valid < 4)
    int soff = tid - skg * WIN;
    bool stager = (tid < NKG * WIN);

    const unsigned* packu = (const unsigned*)g_pack;
    int vrow0 = (b * NV) * NRP + rp0;

    unsigned long long acc[2][2][NPAIR];
    #pragma unroll
    for (int py = 0; py < 2; ++py)
        #pragma unroll
        for (int px = 0; px < 2; ++px)
            #pragma unroll
            for (int k = 0; k < NPAIR; ++k)
                acc[py][px][k] = 0ull;

    const __half2 ones2 = __floats2half2_rn(1.0f, 1.0f);

    __syncthreads();   // tables ready (also makes swin visible to stagers)

    // stage views v, v+1 into ring buffer bi (windows from swin[])
    auto stage = [&](int bi, int v) {
        if (!stager) return;
        int wa = swin[v], wb = swin[v + 1];
        int pA = (vrow0 + v * NRP + 2 * skg) * NC;       // pair 2*skg, view v
        int pB = pA + NC;
        {
            int gi = wa + soff;
            uint4 q;
            q.x = packu[pA + gi];
            q.y = packu[pA + gi + 1];
            q.z = packu[pB + gi];
            q.w = packu[pB + gi + 1];
            sp[bi][0][soff][skg] = q;
        }
        {
            int pA1 = pA + NRP * NC;
            int pB1 = pB + NRP * NC;
            int gi = wb + soff;
            uint4 q;
            q.x = packu[pA1 + gi];
            q.y = packu[pA1 + gi + 1];
            q.z = packu[pB1 + gi];
            q.w = packu[pB1 + gi + 1];
            sp[bi][1][soff][skg] = q;
        }
    };

    // prologue: stage iterations 0 and 1
    stage(0, 0);
    stage(1, 2);
    __syncthreads();

    for (int it = 0; it < NV / 2; ++it) {
        int buf = it & (NBUF - 1);

        if (it + 2 < NV / 2)
            stage((it + 2) & (NBUF - 1), 2 * it + 4);

        int v = 2 * it;
        float c0 = scos[v],     s0 = ssin[v];
        float c1 = scos[v + 1], s1 = ssin[v + 1];
        int   w0 = swin[v],     w1 = swin[v + 1];

        float t000 = fmaf(xb, c0, fmaf(yb, s0, 255.5f));
        float t001 = fmaf(xb, c1, fmaf(yb, s1, 255.5f));
        float c160 = 16.0f * c0, s160 = 16.0f * s0;
        float c161 = 16.0f * c1, s161 = 16.0f * s1;

        #pragma unroll
        for (int py = 0; py < 2; ++py) {
            #pragma unroll
            for (int px = 0; px < 2; ++px) {
                float ta = t000 + (float)px * c160 + (float)py * s160;
                ta = fminf(fmaxf(ta, 0.0f), 511.0f);
                int ia = __float2int_rd(ta);
                float wa = ta - (float)ia;
                int la = ia - w0;
                __half2 wab  = __float2half2_rn(wa);
                __half2 wab1 = __hsub2(ones2, wab);

                float tb = t001 + (float)px * c161 + (float)py * s161;
                tb = fminf(fmaxf(tb, 0.0f), 511.0f);
                int ib = __float2int_rd(tb);
                float wb = tb - (float)ib;
                int lb = ib - w1;
                __half2 wbb  = __float2half2_rn(wb);
                __half2 wbb1 = __hsub2(ones2, wbb);

                // hoist all 8 loads (both views x 4 kg) -> deep MLP
                uint4 qa[NKG], qb[NKG];
                #pragma unroll
                for (int kg = 0; kg < NKG; ++kg) qa[kg] = sp[buf][0][la][kg];
                #pragma unroll
                for (int kg = 0; kg < NKG; ++kg) qb[kg] = sp[buf][1][lb][kg];

                #pragma unroll
                for (int kg = 0; kg < NKG; ++kg) {
                    // pair A = 2*kg
                    __half2 vA;
                    vA = __hmul2(*(__half2*)&qa[kg].x, wab1);
                    vA = __hfma2(*(__half2*)&qa[kg].y, wab, vA);
                    vA = __hfma2(*(__half2*)&qb[kg].x, wbb1, vA);
                    vA = __hfma2(*(__half2*)&qb[kg].y, wbb, vA);
                    float2 fA = __half22float2(vA);
                    unsigned long long vpA;
                    asm("mov.b64 %0, {%1, %2};" : "=l"(vpA) : "f"(fA.x), "f"(fA.y));
                    asm("add.rn.f32x2 %0, %0, %1;" : "+l"(acc[py][px][2 * kg]) : "l"(vpA));
                    // pair B = 2*kg+1
                    __half2 vB;
                    vB = __hmul2(*(__half2*)&qa[kg].z, wab1);
                    vB = __hfma2(*(__half2*)&qa[kg].w, wab, vB);
                    vB = __hfma2(*(__half2*)&qb[kg].z, wbb1, vB);
                    vB = __hfma2(*(__half2*)&qb[kg].w, wbb, vB);
                    float2 fB = __half22float2(vB);
                    unsigned long long vpB;
                    asm("mov.b64 %0, {%1, %2};" : "=l"(vpB) : "f"(fB.x), "f"(fB.y));
                    asm("add.rn.f32x2 %0, %0, %1;" : "+l"(acc[py][px][2 * kg + 1]) : "l"(vpB));
                }
            }
        }

        __syncthreads();
    }

    const float outscale = (float)(PI_D / (double)NV);
    #pragma unroll
    for (int k = 0; k < NPAIR; ++k) {
        #pragma unroll
        for (int py = 0; py < 2; ++py) {
            #pragma unroll
            for (int px = 0; px < 2; ++px) {
                int y = y0 + ty + py * 16;
                int x = x0 + tx + px * 16;
                int imgA = r0 + 2 * k;
                float ax, ay;
                asm("mov.b64 {%0, %1}, %2;" : "=f"(ax), "=f"(ay) : "l"(acc[py][px][k]));
                float va = fmaxf(ax * outscale, 0.0f);
                float vb = fmaxf(ay * outscale, 0.0f);
                out[(((b * NR + imgA) * NPIX) + y) * NPIX + x] = va;
                out[(((b * NR + imgA + 1) * NPIX) + y) * NPIX + x] = vb;
            }
        }
    }
}

extern "C" void kernel_launch(void* const* d_in, const int* in_sizes, int n_in,
                              void* d_out, int out_size) {
    const float* sino = (const float*)d_in[0];
    float* out = (float*)d_out;
    (void)in_sizes; (void)n_in; (void)out_size;

    filter_kernel<<<NB * NV * NR / 2, 256>>>(sino);
    dim3 bpGrid(NPIX / TILE, NPIX / TILE, (NB * NR) / (2 * NPAIR));
    backproj_kernel<<<bpGrid, 256>>>(out);   // 1-D 256-thread block
}